// round 6
// baseline (speedup 1.0000x reference)
#include <cuda_runtime.h>
#include <cstdint>
#include <math.h>

// Problem constants
#define T_STEPS 512
#define BATCH   64
#define NHID    2048
#define NINP    64
#define NOUT    64

// Kernel config
#define NB 128                    // persistent CTAs (<=148 SMs, 1 CTA/SM -> all co-resident)
#define NT 128                    // threads per CTA
#define HT 16                     // h columns per CTA (NB*HT == NHID)
#define KC 128                    // k chunk (double buffered)
#define NCHUNK (NHID / KC)        // 16
#define CHUNK_FLOATS (KC * BATCH) // 8192 floats = 32 KB

// smem: sbuf(2 chunks) + Wh stripe + x_t + Wi stripe
#define SMEM_FLOATS (2 * CHUNK_FLOATS + HT * NHID + NINP * BATCH + HT * NINP)
#define SMEM_BYTES  (SMEM_FLOATS * 4)   // 217088

// State double buffer, TRANSPOSED: g_sT[buf][h*BATCH + b]
__device__ float    g_sT[2][NHID * BATCH];
// x transposed: g_xT[t][i*BATCH + b]
__device__ float    g_xT[T_STEPS * NINP * BATCH];
__device__ unsigned g_bar;

// ---------------- prologue kernels ----------------
__global__ void reset_kernel() { g_bar = 0u; }

__global__ void transpose_x_kernel(const float* __restrict__ x) {
    __shared__ float xs[BATCH * (NINP + 1)];
    const int t = blockIdx.x;
    const float* xt = x + (size_t)t * (BATCH * NINP);
    for (int idx = threadIdx.x; idx < BATCH * NINP; idx += blockDim.x) {
        int b = idx >> 6, i = idx & 63;          // src [b][i], coalesced read
        xs[b * (NINP + 1) + i] = xt[idx];
    }
    __syncthreads();
    float* dst = g_xT + (size_t)t * (NINP * BATCH);
    for (int idx = threadIdx.x; idx < NINP * BATCH; idx += blockDim.x) {
        int i = idx >> 6, b = idx & 63;          // dst [i][b], coalesced write
        dst[idx] = xs[b * (NINP + 1) + i];       // padded -> conflict-free
    }
}

// ---------------- helpers ----------------
__device__ __forceinline__ void cpa16(float* s, const float* g) {
    unsigned sa = (unsigned)__cvta_generic_to_shared(s);
    asm volatile("cp.async.cg.shared.global [%0], [%1], 16;" :: "r"(sa), "l"(g) : "memory");
}
__device__ __forceinline__ void cpa_commit() { asm volatile("cp.async.commit_group;" ::: "memory"); }
__device__ __forceinline__ void cpa_wait1()  { asm volatile("cp.async.wait_group 1;" ::: "memory"); }
__device__ __forceinline__ void cpa_wait0()  { asm volatile("cp.async.wait_group 0;" ::: "memory"); }

__device__ __forceinline__ unsigned long long pk2(float v) {
    unsigned long long r;
    asm("mov.b64 %0, {%1, %1};" : "=l"(r) : "f"(v));
    return r;
}
__device__ __forceinline__ void fma2(unsigned long long& d, unsigned long long a, unsigned long long b) {
    asm("fma.rn.f32x2 %0, %1, %2, %0;" : "+l"(d) : "l"(a), "l"(b));
}
__device__ __forceinline__ float2 upk(unsigned long long v) {
    float2 r;
    asm("mov.b64 {%0, %1}, %2;" : "=f"(r.x), "=f"(r.y) : "l"(v));
    return r;
}

// Grid barrier: monotone counter zeroed each launch by reset_kernel.
__device__ __forceinline__ void gbar(unsigned target, int tid) {
    __threadfence();            // release this CTA's state stores (gpu scope)
    __syncthreads();
    if (tid == 0) {
        atomicAdd(&g_bar, 1u);
        unsigned v;
        do {
            asm volatile("ld.acquire.gpu.u32 %0, [%1];" : "=r"(v) : "l"(&g_bar) : "memory");
        } while (v < target);
    }
    __syncthreads();
}

// ---------------- persistent recurrence kernel ----------------
__global__ void __launch_bounds__(NT, 1) rnn_kernel(
    const float* __restrict__ Wi,   // [NHID][NINP]
    const float* __restrict__ Wib,  // [NHID]
    const float* __restrict__ Wh,   // [NHID][NHID]
    const float* __restrict__ Ag,   // [NHID]
    const float* __restrict__ Om)   // [NHID]
{
    extern __shared__ float sm[];
    float* sbuf = sm;                        // 2 * 8192 floats (16B aligned)
    float* whs  = sm + 2 * CHUNK_FLOATS;     // HT*NHID, layout [k][hl]
    float* xbuf = whs + HT * NHID;           // NINP*BATCH, layout [i][b]
    float* wis  = xbuf + NINP * BATCH;       // NINP*HT,   layout [i][hl]

    const int tid = threadIdx.x;
    const int bq  = tid & 15;                // b group: b = bq*4 .. bq*4+3
    const int hq  = tid >> 4;                // h group: hl = hq*2, hq*2+1
    const int h0g = blockIdx.x * HT;
    const int hl0 = hq * 2;

    // One-time loads: Wh stripe (k-major), Wi stripe (i-major), state init = 1
    for (int idx = tid; idx < HT * NHID; idx += NT) {
        int hl = idx >> 11;                  // / NHID
        int k  = idx & (NHID - 1);
        whs[k * HT + hl] = Wh[(size_t)(h0g + hl) * NHID + k];
    }
    for (int idx = tid; idx < HT * NINP; idx += NT) {
        int hl = idx >> 6;
        int i  = idx & 63;
        wis[i * HT + hl] = Wi[(h0g + hl) * NINP + i];
    }
    for (int idx = tid; idx < HT * BATCH; idx += NT) {
        g_sT[0][(h0g + (idx >> 6)) * BATCH + (idx & 63)] = 1.0f;
    }

    const float A0  = Ag[h0g + hl0], A1  = Ag[h0g + hl0 + 1];
    const float o0  = Om[h0g + hl0], o1  = Om[h0g + hl0 + 1];
    const float bi0 = Wib[h0g + hl0], bi1 = Wib[h0g + hl0 + 1];

    float st[2][4];
    #pragma unroll
    for (int h = 0; h < 2; ++h)
        #pragma unroll
        for (int j = 0; j < 4; ++j) st[h][j] = 1.0f;

    unsigned ph = 1;
    gbar(ph * NB, tid); ++ph;               // init barrier: all state-0 slices visible

    for (int t = 0; t < T_STEPS; ++t) {
        const int cur = t & 1, nxt = cur ^ 1;
        const float* S = g_sT[cur];

        // stage x_t (group A, 4096 floats = 1024 vec4) and chunk 0 (group B)
        {
            const float* xsrc = g_xT + (size_t)t * (NINP * BATCH);
            #pragma unroll
            for (int j = 0; j < 8; ++j) { int v = tid + j * NT; cpa16(xbuf + v * 4, xsrc + v * 4); }
            cpa_commit();
            #pragma unroll
            for (int j = 0; j < 16; ++j) { int v = tid + j * NT; cpa16(sbuf + v * 4, S + v * 4); }
            cpa_commit();
        }

        unsigned long long m00 = pk2(0.f), m01 = pk2(0.f), m10 = pk2(0.f), m11 = pk2(0.f);
        int buf = 0;

        for (int c = 0; c < NCHUNK; ++c) {
            if (c + 1 < NCHUNK) {
                const float* src = S + (c + 1) * CHUNK_FLOATS;
                float* dst = sbuf + (buf ^ 1) * CHUNK_FLOATS;
                #pragma unroll
                for (int j = 0; j < 16; ++j) { int v = tid + j * NT; cpa16(dst + v * 4, src + v * 4); }
                cpa_commit();
                cpa_wait1();                 // chunk c (and x by c=0) has landed
            } else {
                cpa_wait0();                 // everything landed (incl. x)
            }
            __syncthreads();

            const ulonglong2* sb = (const ulonglong2*)(sbuf + buf * CHUNK_FLOATS);
            const float2* wv = (const float2*)whs + c * KC * (HT / 2) + hq;
            #pragma unroll 8
            for (int kk = 0; kk < KC; ++kk) {
                ulonglong2 sv = sb[kk * 16 + bq];          // LDS.128: state[k][b0..b3]
                float2 w = wv[kk * (HT / 2)];              // LDS.64 : Wh[h0..h1][k] (broadcast)
                unsigned long long w0 = pk2(w.x), w1 = pk2(w.y);
                fma2(m00, sv.x, w0); fma2(m01, sv.y, w0);
                fma2(m10, sv.x, w1); fma2(m11, sv.y, w1);
            }
            __syncthreads();                 // protect buf before it's refilled next iter
            buf ^= 1;
        }

        // u_t = Wi x_t + b for this thread's (2h x 4b) tile
        float ua[2][4];
        #pragma unroll
        for (int j = 0; j < 4; ++j) { ua[0][j] = bi0; ua[1][j] = bi1; }
        const float4* xv = (const float4*)xbuf;
        #pragma unroll 4
        for (int i = 0; i < NINP; ++i) {
            float4 xs = xv[i * 16 + bq];
            float w0 = wis[i * HT + hl0], w1 = wis[i * HT + hl0 + 1];
            ua[0][0] += xs.x * w0; ua[0][1] += xs.y * w0; ua[0][2] += xs.z * w0; ua[0][3] += xs.w * w0;
            ua[1][0] += xs.x * w1; ua[1][1] += xs.y * w1; ua[1][2] += xs.z * w1; ua[1][3] += xs.w * w1;
        }

        // epilogue: new = A*cos(omega*old + u) + matmul; store + carry in regs
        float2 p00 = upk(m00), p01 = upk(m01), p10 = upk(m10), p11 = upk(m11);
        float mm[2][4] = { { p00.x, p00.y, p01.x, p01.y },
                           { p10.x, p10.y, p11.x, p11.y } };
        float ns[2][4];
        #pragma unroll
        for (int j = 0; j < 4; ++j) {
            ns[0][j] = A0 * cosf(o0 * st[0][j] + ua[0][j]) + mm[0][j];
            ns[1][j] = A1 * cosf(o1 * st[1][j] + ua[1][j]) + mm[1][j];
        }
        #pragma unroll
        for (int h = 0; h < 2; ++h) {
            float4 v = make_float4(ns[h][0], ns[h][1], ns[h][2], ns[h][3]);
            ((float4*)(g_sT[nxt] + (size_t)(h0g + hl0 + h) * BATCH))[bq] = v;   // coalesced STG.128
            #pragma unroll
            for (int j = 0; j < 4; ++j) st[h][j] = ns[h][j];
        }

        gbar(ph * NB, tid); ++ph;
    }
}

// ---------------- readout: out[b][o] = sum_h sT[h][b]*Wr[o][h] + Wrb[o] ----------------
__global__ void readout_kernel(const float* __restrict__ Wr,
                               const float* __restrict__ Wrb,
                               float* __restrict__ out)
{
    __shared__ float red[256];
    const int o   = blockIdx.x;
    const int b   = threadIdx.x & 63;
    const int hqr = threadIdx.x >> 6;
    const float* S  = g_sT[0];                       // final state buffer (t=511 wrote buf 0)
    const float* wr = Wr + (size_t)o * NHID;
    float acc = 0.f;
    const int h0 = hqr * (NHID / 4), h1 = h0 + (NHID / 4);
    for (int h = h0; h < h1; ++h)
        acc += S[h * BATCH + b] * wr[h];             // S: coalesced over b; wr: broadcast
    red[threadIdx.x] = acc;
    __syncthreads();
    if (hqr == 0)
        out[b * NOUT + o] = red[b] + red[b + 64] + red[b + 128] + red[b + 192] + Wrb[o];
}

// ---------------- launch ----------------
extern "C" void kernel_launch(void* const* d_in, const int* in_sizes, int n_in,
                              void* d_out, int out_size) {
    const float* x   = (const float*)d_in[0];
    const float* Wi  = (const float*)d_in[1];
    const float* Wib = (const float*)d_in[2];
    const float* Wh  = (const float*)d_in[3];
    const float* A   = (const float*)d_in[4];
    const float* Om  = (const float*)d_in[5];
    const float* Wr  = (const float*)d_in[6];
    const float* Wrb = (const float*)d_in[7];
    float* out = (float*)d_out;

    cudaFuncSetAttribute(rnn_kernel, cudaFuncAttributeMaxDynamicSharedMemorySize, SMEM_BYTES);

    reset_kernel<<<1, 1>>>();
    transpose_x_kernel<<<T_STEPS, 256>>>(x);
    rnn_kernel<<<NB, NT, SMEM_BYTES>>>(Wi, Wib, Wh, A, Om);
    readout_kernel<<<NOUT, 256>>>(Wr, Wrb, out);
}